// round 3
// baseline (speedup 1.0000x reference)
#include <cuda_runtime.h>

// Problem constants
#define BB      16
#define TT      1024
#define NK      1024
#define DD      256
#define WIN     64
#define TILE_T  32

// Shared-memory layout (floats). 258-float row stride => row-to-row bank shift
// of 2, making the strided-j K reads conflict-free for LDS.64.
#define QS_STRIDE   258
#define KS_STRIDE   258
#define PS_STRIDE   68

#define QS_OFF      0
#define KS_OFF      (TILE_T * QS_STRIDE)                 // 8256
#define PS_OFF      (KS_OFF + WIN * KS_STRIDE)           // 24768 (16B aligned *4)
#define SMEM_FLOATS (PS_OFF + TILE_T * PS_STRIDE)        // 26944 floats
#define SMEM_BYTES  (SMEM_FLOATS * 4)                    // 107776 B -> 2 CTAs/SM

// Output layout: R (B,T,512) | alignments (B,N,T) | max_attentions (B,T)
#define R_ELEMS   ((size_t)BB * TT * (2 * DD))           // 8,388,608
#define AL_ELEMS  ((size_t)BB * NK * TT)                 // 16,777,216

typedef unsigned long long u64;

union UF2 { u64 u; float2 f; };

// Packed fp32x2 FMA (Blackwell FFMA2) — exact fp32, 2x FFMA throughput.
__device__ __forceinline__ u64 fma2(u64 a, u64 b, u64 c) {
    u64 d;
    asm("fma.rn.f32x2 %0, %1, %2, %3;" : "=l"(d) : "l"(a), "l"(b), "l"(c));
    return d;
}

__global__ __launch_bounds__(256, 2)
void attn_win_kernel(const float* __restrict__ Q,
                     const float* __restrict__ K,
                     const float* __restrict__ V,
                     const int*   __restrict__ prev_words,  // raw words of prev_max_attentions
                     float* __restrict__ out)
{
    extern __shared__ float smem[];
    float* Qs = smem + QS_OFF;
    float* Ks = smem + KS_OFF;
    float* Ps = smem + PS_OFF;

    const int tid = threadIdx.x;
    const int b   = blockIdx.y;
    const int t0  = blockIdx.x * TILE_T;

    // dtype sniff: int64 (little-endian, values < 2^31) has zero high words.
    // Works whether jax emitted int64 or (x64-disabled) int32. Reads only the
    // first 64 bytes, in-bounds for both layouts.
    int odd_or = prev_words[1] | prev_words[3] | prev_words[5] | prev_words[7] |
                 prev_words[9] | prev_words[11] | prev_words[13] | prev_words[15];
    const int prev = (odd_or == 0) ? prev_words[2 * b] : prev_words[b];

    float* Rout = out;                       // (B,T,512)
    float* Aout = out + R_ELEMS;             // (B,N,T), pre-zeroed by memset
    float* Mout = Aout + AL_ELEMS;           // (B,T)

    // ---------------- Load Q tile -> smem, and copy into R[:, :, 256:512] ----
    {
        const float4* Qg = (const float4*)(Q + ((size_t)b * TT + t0) * DD);
        #pragma unroll
        for (int it = 0; it < (TILE_T * DD / 4) / 256; ++it) {   // 8 iters
            int idx = tid + it * 256;
            int t   = idx >> 6;          // 0..31
            int d4  = idx & 63;          // 0..63 (float4 index)
            float4 q4 = __ldg(&Qg[t * 64 + d4]);
            float2* dst = (float2*)(Qs + t * QS_STRIDE + d4 * 4);
            dst[0] = make_float2(q4.x, q4.y);
            dst[1] = make_float2(q4.z, q4.w);
            *(float4*)(Rout + ((size_t)b * TT + t0 + t) * (2 * DD) + DD + d4 * 4) = q4;
        }
    }
    // ---------------- Load K window -> smem ---------------------------------
    {
        const float4* Kg = (const float4*)(K + ((size_t)b * NK + prev) * DD);
        #pragma unroll
        for (int it = 0; it < (WIN * DD / 4) / 256; ++it) {      // 16 iters
            int idx = tid + it * 256;
            int j   = idx >> 6;          // 0..63
            int d4  = idx & 63;
            float4 k4 = __ldg(&Kg[j * 64 + d4]);
            float2* dst = (float2*)(Ks + j * KS_STRIDE + d4 * 4);
            dst[0] = make_float2(k4.x, k4.y);
            dst[1] = make_float2(k4.z, k4.w);
        }
    }
    __syncthreads();

    // ---------------- QK^T: scores[t][j], t in tile(32), j in 0..63 ----------
    // Thread tile: 2 t-rows x 4 strided j-cols (j = jg + 16*jj).
    // Lanes 0..15 hit 16 consecutive K rows (bank-pair shift 2): conflict-free.
    {
        const int jg = tid & 15;
        const int tg = tid >> 4;                    // 0..15 -> rows 2*tg, 2*tg+1
        const u64* q0p = (const u64*)Qs + (size_t)(2 * tg) * (QS_STRIDE / 2);
        const u64* q1p = q0p + (QS_STRIDE / 2);
        const u64* kp  = (const u64*)Ks + (size_t)jg * (KS_STRIDE / 2);
        const int KROW = 16 * (KS_STRIDE / 2);      // 16 rows step in u64 units

        u64 acc[2][4];
        #pragma unroll
        for (int i = 0; i < 2; ++i)
            #pragma unroll
            for (int jj = 0; jj < 4; ++jj) acc[i][jj] = 0ull;

        #pragma unroll 4
        for (int d2 = 0; d2 < DD / 2; ++d2) {
            u64 q0 = q0p[d2];
            u64 q1 = q1p[d2];
            u64 k0 = kp[d2];
            u64 k1 = kp[d2 + KROW];
            u64 k2 = kp[d2 + 2 * KROW];
            u64 k3 = kp[d2 + 3 * KROW];
            acc[0][0] = fma2(q0, k0, acc[0][0]);
            acc[1][0] = fma2(q1, k0, acc[1][0]);
            acc[0][1] = fma2(q0, k1, acc[0][1]);
            acc[1][1] = fma2(q1, k1, acc[1][1]);
            acc[0][2] = fma2(q0, k2, acc[0][2]);
            acc[1][2] = fma2(q1, k2, acc[1][2]);
            acc[0][3] = fma2(q0, k3, acc[0][3]);
            acc[1][3] = fma2(q1, k3, acc[1][3]);
        }
        #pragma unroll
        for (int i = 0; i < 2; ++i)
            #pragma unroll
            for (int jj = 0; jj < 4; ++jj) {
                UF2 u; u.u = acc[i][jj];
                Ps[(2 * tg + i) * PS_STRIDE + jg + 16 * jj] =
                    (u.f.x + u.f.y) * 0.0625f;   // * rsqrt(256)
            }
    }
    __syncthreads();

    // ---------------- softmax over 64 window cols + argmax -------------------
    {
        const int lane = tid & 31;
        const int w    = tid >> 5;                 // 8 warps x 4 rows
        #pragma unroll
        for (int rr = 0; rr < TILE_T / 8; ++rr) {
            int r = w * (TILE_T / 8) + rr;
            float v0 = Ps[r * PS_STRIDE + lane];
            float v1 = Ps[r * PS_STRIDE + lane + 32];
            float bv; int bi;
            if (v0 >= v1) { bv = v0; bi = lane; } else { bv = v1; bi = lane + 32; }
            #pragma unroll
            for (int off = 16; off > 0; off >>= 1) {
                float ov = __shfl_xor_sync(0xffffffffu, bv, off);
                int   oi = __shfl_xor_sync(0xffffffffu, bi, off);
                if (ov > bv || (ov == bv && oi < bi)) { bv = ov; bi = oi; }
            }
            float e0 = expf(v0 - bv);
            float e1 = expf(v1 - bv);
            float s = e0 + e1;
            #pragma unroll
            for (int off = 16; off > 0; off >>= 1)
                s += __shfl_xor_sync(0xffffffffu, s, off);
            float inv = 1.0f / s;
            Ps[r * PS_STRIDE + lane]      = e0 * inv;
            Ps[r * PS_STRIDE + lane + 32] = e1 * inv;
            if (lane == 0)
                Mout[(size_t)b * TT + t0 + r] = (float)(prev + bi);
        }
    }
    __syncthreads();

    // ---------------- scatter probs into alignments (B,N,T) ------------------
    // Coalesced along t (contiguous in alignments rows).
    {
        #pragma unroll
        for (int it = 0; it < (WIN * TILE_T) / 256; ++it) {      // 8 iters
            int idx = tid + it * 256;
            int j   = idx >> 5;          // 0..63
            int ttl = idx & 31;          // 0..31
            Aout[((size_t)b * NK + prev + j) * TT + t0 + ttl] =
                Ps[ttl * PS_STRIDE + j];
        }
    }

    // ---------------- P @ V_window -> R[:, :, 0:256] --------------------------
    // Thread owns 4 t-rows (tg) and two float4 columns: [4*d8, 4*d8+4) and
    // [128+4*d8, ...). V read from global (L2-resident window), coalesced.
    {
        const int d8 = tid & 31;
        const int tg = tid >> 5;                   // 0..7 -> rows 4*tg..+3
        u64 acc[4][4];
        #pragma unroll
        for (int r = 0; r < 4; ++r)
            #pragma unroll
            for (int c = 0; c < 4; ++c) acc[r][c] = 0ull;

        const ulonglong2* Vg =
            (const ulonglong2*)(V + ((size_t)b * NK + prev) * DD);

        #pragma unroll 2
        for (int j4 = 0; j4 < WIN / 4; ++j4) {
            ulonglong2 v[4][2];
            #pragma unroll
            for (int jj = 0; jj < 4; ++jj) {
                const ulonglong2* row = Vg + (size_t)(j4 * 4 + jj) * (DD / 4);
                v[jj][0] = __ldg(&row[d8]);        // floats [4*d8, 4*d8+4)
                v[jj][1] = __ldg(&row[32 + d8]);   // floats [128+4*d8, ...)
            }
            #pragma unroll
            for (int r = 0; r < 4; ++r) {
                float4 p4 = *(const float4*)(Ps + (tg * 4 + r) * PS_STRIDE + j4 * 4);
                float pv[4] = {p4.x, p4.y, p4.z, p4.w};
                #pragma unroll
                for (int jj = 0; jj < 4; ++jj) {
                    UF2 pp; pp.f = make_float2(pv[jj], pv[jj]);
                    acc[r][0] = fma2(pp.u, v[jj][0].x, acc[r][0]);
                    acc[r][1] = fma2(pp.u, v[jj][0].y, acc[r][1]);
                    acc[r][2] = fma2(pp.u, v[jj][1].x, acc[r][2]);
                    acc[r][3] = fma2(pp.u, v[jj][1].y, acc[r][3]);
                }
            }
        }
        #pragma unroll
        for (int r = 0; r < 4; ++r) {
            float* dst = Rout + ((size_t)b * TT + t0 + tg * 4 + r) * (2 * DD);
            *(ulonglong2*)(dst + 4 * d8)       = make_ulonglong2(acc[r][0], acc[r][1]);
            *(ulonglong2*)(dst + 128 + 4 * d8) = make_ulonglong2(acc[r][2], acc[r][3]);
        }
    }
}

extern "C" void kernel_launch(void* const* d_in, const int* in_sizes, int n_in,
                              void* d_out, int out_size)
{
    const float* Q  = (const float*)d_in[0];
    const float* K  = (const float*)d_in[1];
    const float* V  = (const float*)d_in[2];
    const int* prevw = (const int*)d_in[3];   // int64 or int32, sniffed in-kernel
    float* out = (float*)d_out;

    // Zero the alignments region (only 64 of 1024 key rows per batch get
    // written by the kernel; the rest must be exactly 0).
    cudaMemsetAsync(out + R_ELEMS, 0, AL_ELEMS * sizeof(float), 0);

    cudaFuncSetAttribute(attn_win_kernel,
                         cudaFuncAttributeMaxDynamicSharedMemorySize, SMEM_BYTES);

    dim3 grid(TT / TILE_T, BB);
    attn_win_kernel<<<grid, 256, SMEM_BYTES, 0>>>(Q, K, V, prevw, out);
}

// round 5
// speedup vs baseline: 1.0843x; 1.0843x over previous
#include <cuda_runtime.h>

// Problem constants
#define BB      16
#define TT      1024
#define NK      1024
#define DD      256
#define WIN     64
#define TILE_T  32

// Shared-memory layout (floats). 260-float row stride => 4-bank shift per row:
// the 16-lane strided-K LDS.128 reads are exactly 2-phase (optimal), and the
// 2-address broadcast Q LDS.128 reads are 1-phase.
#define QS_STRIDE   260
#define KS_STRIDE   260
#define PS_STRIDE   68

#define QS_OFF      0
#define KS_OFF      (TILE_T * QS_STRIDE)                 // 8320
#define PS_OFF      (KS_OFF + WIN * KS_STRIDE)           // 24960
#define SMEM_FLOATS (PS_OFF + TILE_T * PS_STRIDE)        // 27136 floats
#define SMEM_BYTES  (SMEM_FLOATS * 4)                    // 108544 B -> 2 CTAs/SM

// Output layout: R (B,T,512) | alignments (B,N,T) | max_attentions (B,T)
#define R_ELEMS   ((size_t)BB * TT * (2 * DD))           // 8,388,608
#define AL_ELEMS  ((size_t)BB * NK * TT)                 // 16,777,216

typedef unsigned long long u64;

union UF2 { u64 u; float2 f; };

// Packed fp32x2 FMA (Blackwell FFMA2) — exact fp32, 2x FFMA throughput.
__device__ __forceinline__ u64 fma2(u64 a, u64 b, u64 c) {
    u64 d;
    asm("fma.rn.f32x2 %0, %1, %2, %3;" : "=l"(d) : "l"(a), "l"(b), "l"(c));
    return d;
}

__global__ __launch_bounds__(256, 2)
void attn_win_kernel(const float* __restrict__ Q,
                     const float* __restrict__ K,
                     const float* __restrict__ V,
                     const int*   __restrict__ prev_words,  // raw words of prev_max_attentions
                     float* __restrict__ out)
{
    extern __shared__ float smem[];
    float* Qs = smem + QS_OFF;
    float* Ks = smem + KS_OFF;
    float* Ps = smem + PS_OFF;

    const int tid = threadIdx.x;
    const int b   = blockIdx.y;
    const int t0  = blockIdx.x * TILE_T;

    // dtype sniff: int64 (little-endian, values < 2^31) has zero high words.
    int odd_or = prev_words[1] | prev_words[3] | prev_words[5] | prev_words[7] |
                 prev_words[9] | prev_words[11] | prev_words[13] | prev_words[15];
    const int prev = (odd_or == 0) ? prev_words[2 * b] : prev_words[b];

    float* Rout = out;                       // (B,T,512)
    float* Aout = out + R_ELEMS;             // (B,N,T), zero-filled below
    float* Mout = Aout + AL_ELEMS;           // (B,T)

    // ---------------- Load Q tile -> smem, and copy into R[:, :, 256:512] ----
    {
        const float4* Qg = (const float4*)(Q + ((size_t)b * TT + t0) * DD);
        #pragma unroll
        for (int it = 0; it < (TILE_T * DD / 4) / 256; ++it) {   // 8 iters
            int idx = tid + it * 256;
            int t   = idx >> 6;          // 0..31
            int d4  = idx & 63;          // 0..63 (float4 index)
            float4 q4 = __ldg(&Qg[t * 64 + d4]);
            *(float4*)(Qs + t * QS_STRIDE + d4 * 4) = q4;
            *(float4*)(Rout + ((size_t)b * TT + t0 + t) * (2 * DD) + DD + d4 * 4) = q4;
        }
    }
    // ---------------- Load K window -> smem ---------------------------------
    {
        const float4* Kg = (const float4*)(K + ((size_t)b * NK + prev) * DD);
        #pragma unroll
        for (int it = 0; it < (WIN * DD / 4) / 256; ++it) {      // 16 iters
            int idx = tid + it * 256;
            int j   = idx >> 6;          // 0..63
            int d4  = idx & 63;
            *(float4*)(Ks + j * KS_STRIDE + d4 * 4) = __ldg(&Kg[j * 64 + d4]);
        }
    }
    __syncthreads();

    // ---------------- QK^T: scores[t][j], t in tile(32), j in 0..63 ----------
    // Thread tile: 2 t-rows x 4 strided j-cols (j = jg + 16*jj), float4 loads.
    {
        const int jg = tid & 15;
        const int tg = tid >> 4;                    // 0..15 -> rows 2*tg, 2*tg+1
        const ulonglong2* q0p = (const ulonglong2*)(Qs + (size_t)(2 * tg) * QS_STRIDE);
        const ulonglong2* q1p = (const ulonglong2*)(Qs + (size_t)(2 * tg + 1) * QS_STRIDE);
        const ulonglong2* kp  = (const ulonglong2*)(Ks + (size_t)jg * KS_STRIDE);
        const int KROW = 16 * (KS_STRIDE / 4);      // 16 rows step in ulonglong2 units

        u64 accL[2][4], accH[2][4];
        #pragma unroll
        for (int i = 0; i < 2; ++i)
            #pragma unroll
            for (int jj = 0; jj < 4; ++jj) { accL[i][jj] = 0ull; accH[i][jj] = 0ull; }

        #pragma unroll 2
        for (int d4 = 0; d4 < DD / 4; ++d4) {
            ulonglong2 q0 = q0p[d4];
            ulonglong2 q1 = q1p[d4];
            ulonglong2 k0 = kp[d4];
            ulonglong2 k1 = kp[d4 + KROW];
            ulonglong2 k2 = kp[d4 + 2 * KROW];
            ulonglong2 k3 = kp[d4 + 3 * KROW];
            accL[0][0] = fma2(q0.x, k0.x, accL[0][0]);
            accH[0][0] = fma2(q0.y, k0.y, accH[0][0]);
            accL[1][0] = fma2(q1.x, k0.x, accL[1][0]);
            accH[1][0] = fma2(q1.y, k0.y, accH[1][0]);
            accL[0][1] = fma2(q0.x, k1.x, accL[0][1]);
            accH[0][1] = fma2(q0.y, k1.y, accH[0][1]);
            accL[1][1] = fma2(q1.x, k1.x, accL[1][1]);
            accH[1][1] = fma2(q1.y, k1.y, accH[1][1]);
            accL[0][2] = fma2(q0.x, k2.x, accL[0][2]);
            accH[0][2] = fma2(q0.y, k2.y, accH[0][2]);
            accL[1][2] = fma2(q1.x, k2.x, accL[1][2]);
            accH[1][2] = fma2(q1.y, k2.y, accH[1][2]);
            accL[0][3] = fma2(q0.x, k3.x, accL[0][3]);
            accH[0][3] = fma2(q0.y, k3.y, accH[0][3]);
            accL[1][3] = fma2(q1.x, k3.x, accL[1][3]);
            accH[1][3] = fma2(q1.y, k3.y, accH[1][3]);
        }
        #pragma unroll
        for (int i = 0; i < 2; ++i)
            #pragma unroll
            for (int jj = 0; jj < 4; ++jj) {
                UF2 lo, hi; lo.u = accL[i][jj]; hi.u = accH[i][jj];
                Ps[(2 * tg + i) * PS_STRIDE + jg + 16 * jj] =
                    (lo.f.x + lo.f.y + hi.f.x + hi.f.y) * 0.0625f; // * rsqrt(256)
            }
    }

    // ---------------- zero-fill non-window rows of alignments ----------------
    // (needs no Ps; overlaps the barrier wait / DRAM has headroom)
    {
        const int rown = tid >> 3;          // 0..31
        const int c4   = tid & 7;           // float4 col of the 32 t-cols
        float* base = Aout + (size_t)b * NK * TT + t0 + 4 * c4;
        const float4 z = make_float4(0.f, 0.f, 0.f, 0.f);
        #pragma unroll 4
        for (int pass = 0; pass < NK / 32; ++pass) {
            int n = pass * 32 + rown;
            if ((unsigned)(n - prev) >= WIN)
                *(float4*)(base + (size_t)n * TT) = z;
        }
    }
    __syncthreads();

    // ---------------- softmax over 64 window cols + argmax -------------------
    {
        const int lane = tid & 31;
        const int w    = tid >> 5;                 // 8 warps x 4 rows
        #pragma unroll
        for (int rr = 0; rr < TILE_T / 8; ++rr) {
            int r = w * (TILE_T / 8) + rr;
            float v0 = Ps[r * PS_STRIDE + lane];
            float v1 = Ps[r * PS_STRIDE + lane + 32];
            float bv; int bi;
            if (v0 >= v1) { bv = v0; bi = lane; } else { bv = v1; bi = lane + 32; }
            #pragma unroll
            for (int off = 16; off > 0; off >>= 1) {
                float ov = __shfl_xor_sync(0xffffffffu, bv, off);
                int   oi = __shfl_xor_sync(0xffffffffu, bi, off);
                if (ov > bv || (ov == bv && oi < bi)) { bv = ov; bi = oi; }
            }
            float e0 = __expf(v0 - bv);
            float e1 = __expf(v1 - bv);
            float s = e0 + e1;
            #pragma unroll
            for (int off = 16; off > 0; off >>= 1)
                s += __shfl_xor_sync(0xffffffffu, s, off);
            float inv = 1.0f / s;
            Ps[r * PS_STRIDE + lane]      = e0 * inv;
            Ps[r * PS_STRIDE + lane + 32] = e1 * inv;
            if (lane == 0)
                Mout[(size_t)b * TT + t0 + r] = (float)(prev + bi);
        }
    }
    __syncthreads();

    // ---------------- scatter probs into window rows of alignments -----------
    {
        const int rown = tid >> 3;          // 0..31
        const int c4   = tid & 7;
        float* base = Aout + (size_t)b * NK * TT + t0 + 4 * c4;
        #pragma unroll
        for (int pass = 0; pass < 2; ++pass) {
            int j = pass * 32 + rown;       // 0..63 window col
            int t = 4 * c4;
            float4 v;
            v.x = Ps[(t + 0) * PS_STRIDE + j];
            v.y = Ps[(t + 1) * PS_STRIDE + j];
            v.z = Ps[(t + 2) * PS_STRIDE + j];
            v.w = Ps[(t + 3) * PS_STRIDE + j];
            *(float4*)(base + (size_t)(prev + j) * TT) = v;
        }
    }

    // ---------------- P @ V_window -> R[:, :, 0:256] --------------------------
    // Thread owns 8 t-rows and one float4 d-column (4x lower V redundancy).
    {
        const int d8 = tid & 63;                   // float4 index 0..63
        const int tg = tid >> 6;                   // 0..3 -> rows 8*tg..+7
        u64 acc[8][2];
        #pragma unroll
        for (int r = 0; r < 8; ++r) { acc[r][0] = 0ull; acc[r][1] = 0ull; }

        const ulonglong2* Vg =
            (const ulonglong2*)(V + ((size_t)b * NK + prev) * DD);

        #pragma unroll 2
        for (int j4 = 0; j4 < WIN / 4; ++j4) {
            ulonglong2 vv[4];
            #pragma unroll
            for (int jj = 0; jj < 4; ++jj)
                vv[jj] = __ldg(&Vg[(size_t)(j4 * 4 + jj) * (DD / 4) + d8]);
            #pragma unroll
            for (int r = 0; r < 8; ++r) {
                float4 p4 = *(const float4*)(Ps + (tg * 8 + r) * PS_STRIDE + j4 * 4);
                UF2 pp;
                pp.f = make_float2(p4.x, p4.x);
                acc[r][0] = fma2(pp.u, vv[0].x, acc[r][0]);
                acc[r][1] = fma2(pp.u, vv[0].y, acc[r][1]);
                pp.f = make_float2(p4.y, p4.y);
                acc[r][0] = fma2(pp.u, vv[1].x, acc[r][0]);
                acc[r][1] = fma2(pp.u, vv[1].y, acc[r][1]);
                pp.f = make_float2(p4.z, p4.z);
                acc[r][0] = fma2(pp.u, vv[2].x, acc[r][0]);
                acc[r][1] = fma2(pp.u, vv[2].y, acc[r][1]);
                pp.f = make_float2(p4.w, p4.w);
                acc[r][0] = fma2(pp.u, vv[3].x, acc[r][0]);
                acc[r][1] = fma2(pp.u, vv[3].y, acc[r][1]);
            }
        }
        #pragma unroll
        for (int r = 0; r < 8; ++r) {
            float* dst = Rout + ((size_t)b * TT + t0 + tg * 8 + r) * (2 * DD) + 4 * d8;
            *(ulonglong2*)dst = make_ulonglong2(acc[r][0], acc[r][1]);
        }
    }
}

extern "C" void kernel_launch(void* const* d_in, const int* in_sizes, int n_in,
                              void* d_out, int out_size)
{
    const float* Q  = (const float*)d_in[0];
    const float* K  = (const float*)d_in[1];
    const float* V  = (const float*)d_in[2];
    const int* prevw = (const int*)d_in[3];   // int64 or int32, sniffed in-kernel
    float* out = (float*)d_out;

    cudaFuncSetAttribute(attn_win_kernel,
                         cudaFuncAttributeMaxDynamicSharedMemorySize, SMEM_BYTES);

    dim3 grid(TT / TILE_T, BB);
    attn_win_kernel<<<grid, 256, SMEM_BYTES, 0>>>(Q, K, V, prevw, out);
}

// round 7
// speedup vs baseline: 1.1930x; 1.1002x over previous
#include <cuda_runtime.h>

// Problem constants
#define BB      16
#define TT      1024
#define NK      1024
#define DD      256
#define WIN     64
#define TILE_T  32

// Shared-memory layout (floats). 260-float row stride => 4-bank shift per row:
// the 16-lane strided-K LDS.128 reads are exactly 2-phase (optimal), and the
// 2-address broadcast Q LDS.128 reads are 1-phase.
#define QS_STRIDE   260
#define KS_STRIDE   260
#define PS_STRIDE   68

#define QS_OFF      0
#define KS_OFF      (TILE_T * QS_STRIDE)                 // 8320
#define PS_OFF      (KS_OFF + WIN * KS_STRIDE)           // 24960
#define SMEM_FLOATS (PS_OFF + TILE_T * PS_STRIDE)        // 27136 floats
#define SMEM_BYTES  (SMEM_FLOATS * 4)                    // 108544 B -> 2 CTAs/SM

// Output layout: R (B,T,512) | alignments (B,N,T) | max_attentions (B,T)
#define R_ELEMS   ((size_t)BB * TT * (2 * DD))           // 8,388,608
#define AL_ELEMS  ((size_t)BB * NK * TT)                 // 16,777,216

typedef unsigned long long u64;
typedef unsigned int       u32;

union UF2 { u64 u; float2 f; };

// Packed fp32x2 FMA (Blackwell FFMA2) — exact fp32, 2x FFMA throughput.
__device__ __forceinline__ u64 fma2(u64 a, u64 b, u64 c) {
    u64 d;
    asm("fma.rn.f32x2 %0, %1, %2, %3;" : "=l"(d) : "l"(a), "l"(b), "l"(c));
    return d;
}

// 16-byte async global->shared copy (LDGSTS): no register pressure, overlaps
// with compute between issue and wait.
__device__ __forceinline__ void cp_async16(u32 smem_addr, const void* gptr) {
    asm volatile("cp.async.cg.shared.global [%0], [%1], 16;"
                 :: "r"(smem_addr), "l"(gptr));
}
__device__ __forceinline__ void cp_async_commit() {
    asm volatile("cp.async.commit_group;");
}
__device__ __forceinline__ void cp_async_wait_all() {
    asm volatile("cp.async.wait_group 0;");
}

__global__ __launch_bounds__(256, 2)
void attn_win_kernel(const float* __restrict__ Q,
                     const float* __restrict__ K,
                     const float* __restrict__ V,
                     const int*   __restrict__ prev_words,  // raw words of prev_max_attentions
                     float* __restrict__ out)
{
    extern __shared__ float smem[];
    float* Qs = smem + QS_OFF;
    float* Ks = smem + KS_OFF;   // K window during QK, then reused for V window
    float* Ps = smem + PS_OFF;

    const int tid = threadIdx.x;
    const int b   = blockIdx.y;
    const int t0  = blockIdx.x * TILE_T;

    // dtype sniff: int64 (little-endian, values < 2^31) has zero high words.
    int odd_or = prev_words[1] | prev_words[3] | prev_words[5] | prev_words[7] |
                 prev_words[9] | prev_words[11] | prev_words[13] | prev_words[15];
    const int prev = (odd_or == 0) ? prev_words[2 * b] : prev_words[b];

    float* Rout = out;                       // (B,T,512)
    float* Aout = out + R_ELEMS;             // (B,N,T), zero-filled below
    float* Mout = Aout + AL_ELEMS;           // (B,T)

    // ---------------- K window -> smem via cp.async (starts first) -----------
    {
        const char* Kg = (const char*)(K + ((size_t)b * NK + prev) * DD);
        #pragma unroll
        for (int it = 0; it < (WIN * DD / 4) / 256; ++it) {      // 16 iters
            int idx = tid + it * 256;
            int j   = idx >> 6;          // 0..63
            int d4  = idx & 63;
            u32 dst = (u32)__cvta_generic_to_shared(Ks + j * KS_STRIDE + d4 * 4);
            cp_async16(dst, Kg + (size_t)(j * 64 + d4) * 16);
        }
        cp_async_commit();
    }
    // ---------------- Q tile -> smem, and copy into R[:, :, 256:512] ---------
    // Overlaps with the in-flight K cp.asyncs.
    {
        const float4* Qg = (const float4*)(Q + ((size_t)b * TT + t0) * DD);
        #pragma unroll
        for (int it = 0; it < (TILE_T * DD / 4) / 256; ++it) {   // 8 iters
            int idx = tid + it * 256;
            int t   = idx >> 6;          // 0..31
            int d4  = idx & 63;          // 0..63 (float4 index)
            float4 q4 = __ldg(&Qg[t * 64 + d4]);
            *(float4*)(Qs + t * QS_STRIDE + d4 * 4) = q4;
            __stcs((float4*)(Rout + ((size_t)b * TT + t0 + t) * (2 * DD) + DD + d4 * 4), q4);
        }
    }
    cp_async_wait_all();
    __syncthreads();

    // ---------------- QK^T: scores[t][j], t in tile(32), j in 0..63 ----------
    // Thread tile: 2 t-rows x 4 strided j-cols (j = jg + 16*jj), float4 loads.
    {
        const int jg = tid & 15;
        const int tg = tid >> 4;                    // 0..15 -> rows 2*tg, 2*tg+1
        const ulonglong2* q0p = (const ulonglong2*)(Qs + (size_t)(2 * tg) * QS_STRIDE);
        const ulonglong2* q1p = (const ulonglong2*)(Qs + (size_t)(2 * tg + 1) * QS_STRIDE);
        const ulonglong2* kp  = (const ulonglong2*)(Ks + (size_t)jg * KS_STRIDE);
        const int KROW = 16 * (KS_STRIDE / 4);      // 16 rows step in ulonglong2 units

        u64 accL[2][4], accH[2][4];
        #pragma unroll
        for (int i = 0; i < 2; ++i)
            #pragma unroll
            for (int jj = 0; jj < 4; ++jj) { accL[i][jj] = 0ull; accH[i][jj] = 0ull; }

        #pragma unroll 2
        for (int d4 = 0; d4 < DD / 4; ++d4) {
            ulonglong2 q0 = q0p[d4];
            ulonglong2 q1 = q1p[d4];
            ulonglong2 k0 = kp[d4];
            ulonglong2 k1 = kp[d4 + KROW];
            ulonglong2 k2 = kp[d4 + 2 * KROW];
            ulonglong2 k3 = kp[d4 + 3 * KROW];
            accL[0][0] = fma2(q0.x, k0.x, accL[0][0]);
            accH[0][0] = fma2(q0.y, k0.y, accH[0][0]);
            accL[1][0] = fma2(q1.x, k0.x, accL[1][0]);
            accH[1][0] = fma2(q1.y, k0.y, accH[1][0]);
            accL[0][1] = fma2(q0.x, k1.x, accL[0][1]);
            accH[0][1] = fma2(q0.y, k1.y, accH[0][1]);
            accL[1][1] = fma2(q1.x, k1.x, accL[1][1]);
            accH[1][1] = fma2(q1.y, k1.y, accH[1][1]);
            accL[0][2] = fma2(q0.x, k2.x, accL[0][2]);
            accH[0][2] = fma2(q0.y, k2.y, accH[0][2]);
            accL[1][2] = fma2(q1.x, k2.x, accL[1][2]);
            accH[1][2] = fma2(q1.y, k2.y, accH[1][2]);
            accL[0][3] = fma2(q0.x, k3.x, accL[0][3]);
            accH[0][3] = fma2(q0.y, k3.y, accH[0][3]);
            accL[1][3] = fma2(q1.x, k3.x, accL[1][3]);
            accH[1][3] = fma2(q1.y, k3.y, accH[1][3]);
        }
        #pragma unroll
        for (int i = 0; i < 2; ++i)
            #pragma unroll
            for (int jj = 0; jj < 4; ++jj) {
                UF2 lo, hi; lo.u = accL[i][jj]; hi.u = accH[i][jj];
                Ps[(2 * tg + i) * PS_STRIDE + jg + 16 * jj] =
                    (lo.f.x + lo.f.y + hi.f.x + hi.f.y) * 0.0625f; // * rsqrt(256)
            }
    }
    __syncthreads();   // Ks (K data) now dead; Ps scores complete

    // ---------------- V window -> smem (reusing Ks) via cp.async -------------
    // Issued first so the copies fly while we zero-fill + run softmax.
    {
        const char* Vg = (const char*)(V + ((size_t)b * NK + prev) * DD);
        #pragma unroll
        for (int it = 0; it < (WIN * DD / 4) / 256; ++it) {      // 16 iters
            int idx = tid + it * 256;
            int j   = idx >> 6;          // 0..63
            int d4  = idx & 63;
            u32 dst = (u32)__cvta_generic_to_shared(Ks + j * KS_STRIDE + d4 * 4);
            cp_async16(dst, Vg + (size_t)(j * 64 + d4) * 16);
        }
        cp_async_commit();
    }

    // ---------------- zero-fill non-window rows of alignments ----------------
    // Independent of smem; drains to DRAM while V copies + softmax proceed.
    {
        const int rown = tid >> 3;          // 0..31
        const int c4   = tid & 7;           // float4 col of the 32 t-cols
        float* base = Aout + (size_t)b * NK * TT + t0 + 4 * c4;
        const float4 z = make_float4(0.f, 0.f, 0.f, 0.f);
        #pragma unroll 4
        for (int pass = 0; pass < NK / 32; ++pass) {
            int n = pass * 32 + rown;
            if ((unsigned)(n - prev) >= WIN)
                __stcs((float4*)(base + (size_t)n * TT), z);
        }
    }

    // ---------------- softmax over 64 window cols + argmax -------------------
    {
        const int lane = tid & 31;
        const int w    = tid >> 5;                 // 8 warps x 4 rows
        #pragma unroll
        for (int rr = 0; rr < TILE_T / 8; ++rr) {
            int r = w * (TILE_T / 8) + rr;
            float v0 = Ps[r * PS_STRIDE + lane];
            float v1 = Ps[r * PS_STRIDE + lane + 32];
            float bv; int bi;
            if (v0 >= v1) { bv = v0; bi = lane; } else { bv = v1; bi = lane + 32; }
            #pragma unroll
            for (int off = 16; off > 0; off >>= 1) {
                float ov = __shfl_xor_sync(0xffffffffu, bv, off);
                int   oi = __shfl_xor_sync(0xffffffffu, bi, off);
                if (ov > bv || (ov == bv && oi < bi)) { bv = ov; bi = oi; }
            }
            float e0 = __expf(v0 - bv);
            float e1 = __expf(v1 - bv);
            float s = e0 + e1;
            #pragma unroll
            for (int off = 16; off > 0; off >>= 1)
                s += __shfl_xor_sync(0xffffffffu, s, off);
            float inv = 1.0f / s;
            Ps[r * PS_STRIDE + lane]      = e0 * inv;
            Ps[r * PS_STRIDE + lane + 32] = e1 * inv;
            if (lane == 0)
                Mout[(size_t)b * TT + t0 + r] = (float)(prev + bi);
        }
    }
    cp_async_wait_all();
    __syncthreads();   // probs + V-in-smem visible to all

    // ---------------- scatter probs into window rows of alignments -----------
    {
        const int rown = tid >> 3;          // 0..31
        const int c4   = tid & 7;
        float* base = Aout + (size_t)b * NK * TT + t0 + 4 * c4;
        #pragma unroll
        for (int pass = 0; pass < 2; ++pass) {
            int j = pass * 32 + rown;       // 0..63 window col
            int t = 4 * c4;
            float4 v;
            v.x = Ps[(t + 0) * PS_STRIDE + j];
            v.y = Ps[(t + 1) * PS_STRIDE + j];
            v.z = Ps[(t + 2) * PS_STRIDE + j];
            v.w = Ps[(t + 3) * PS_STRIDE + j];
            __stcs((float4*)(base + (size_t)(prev + j) * TT), v);
        }
    }

    // ---------------- P @ V_window -> R[:, :, 0:256] --------------------------
    // V now in smem (29-cyc LDS, contiguous 512B/warp => conflict-free).
    // Thread owns 8 t-rows and one float4 d-column.
    {
        const int d8 = tid & 63;                   // float4 index 0..63
        const int tg = tid >> 6;                   // 0..3 -> rows 8*tg..+7
        u64 acc[8][2];
        #pragma unroll
        for (int r = 0; r < 8; ++r) { acc[r][0] = 0ull; acc[r][1] = 0ull; }

        #pragma unroll 2
        for (int j4 = 0; j4 < WIN / 4; ++j4) {
            ulonglong2 vv[4];
            #pragma unroll
            for (int jj = 0; jj < 4; ++jj)
                vv[jj] = *(const ulonglong2*)(Ks + (size_t)(j4 * 4 + jj) * KS_STRIDE + d8 * 4);
            #pragma unroll
            for (int r = 0; r < 8; ++r) {
                float4 p4 = *(const float4*)(Ps + (tg * 8 + r) * PS_STRIDE + j4 * 4);
                UF2 pp;
                pp.f = make_float2(p4.x, p4.x);
                acc[r][0] = fma2(pp.u, vv[0].x, acc[r][0]);
                acc[r][1] = fma2(pp.u, vv[0].y, acc[r][1]);
                pp.f = make_float2(p4.y, p4.y);
                acc[r][0] = fma2(pp.u, vv[1].x, acc[r][0]);
                acc[r][1] = fma2(pp.u, vv[1].y, acc[r][1]);
                pp.f = make_float2(p4.z, p4.z);
                acc[r][0] = fma2(pp.u, vv[2].x, acc[r][0]);
                acc[r][1] = fma2(pp.u, vv[2].y, acc[r][1]);
                pp.f = make_float2(p4.w, p4.w);
                acc[r][0] = fma2(pp.u, vv[3].x, acc[r][0]);
                acc[r][1] = fma2(pp.u, vv[3].y, acc[r][1]);
            }
        }
        #pragma unroll
        for (int r = 0; r < 8; ++r) {
            float* dst = Rout + ((size_t)b * TT + t0 + tg * 8 + r) * (2 * DD) + 4 * d8;
            __stcs((float2*)dst,     *(float2*)&acc[r][0]);
            __stcs((float2*)dst + 1, *(float2*)&acc[r][1]);
        }
    }
}

extern "C" void kernel_launch(void* const* d_in, const int* in_sizes, int n_in,
                              void* d_out, int out_size)
{
    const float* Q  = (const float*)d_in[0];
    const float* K  = (const float*)d_in[1];
    const float* V  = (const float*)d_in[2];
    const int* prevw = (const int*)d_in[3];   // int64 or int32, sniffed in-kernel
    float* out = (float*)d_out;

    cudaFuncSetAttribute(attn_win_kernel,
                         cudaFuncAttributeMaxDynamicSharedMemorySize, SMEM_BYTES);

    dim3 grid(TT / TILE_T, BB);
    attn_win_kernel<<<grid, 256, SMEM_BYTES, 0>>>(Q, K, V, prevw, out);
}

// round 8
// speedup vs baseline: 1.2347x; 1.0350x over previous
#include <cuda_runtime.h>

// Problem constants
#define BB      16
#define TT      1024
#define NK      1024
#define DD      256
#define WIN     64
#define TILE_T  32

// Shared-memory layout (floats). 260-float row stride => 4-bank shift per row.
// QK retile: K loads touch 8 consecutive rows (bank groups 0,4,..,28 -> 1 phase),
// Q loads touch 4 rows spaced 8 banks apart (1 phase).
#define QS_STRIDE   260
#define KS_STRIDE   260
#define PS_STRIDE   68

#define QS_OFF      0
#define KS_OFF      (TILE_T * QS_STRIDE)                 // 8320
#define PS_OFF      (KS_OFF + WIN * KS_STRIDE)           // 24960
#define SMEM_FLOATS (PS_OFF + TILE_T * PS_STRIDE)        // 27136 floats
#define SMEM_BYTES  (SMEM_FLOATS * 4)                    // 108544 B -> 2 CTAs/SM

// Output layout: R (B,T,512) | alignments (B,N,T) | max_attentions (B,T)
#define R_ELEMS   ((size_t)BB * TT * (2 * DD))           // 8,388,608
#define AL_ELEMS  ((size_t)BB * NK * TT)                 // 16,777,216

typedef unsigned long long u64;
typedef unsigned int       u32;

union UF2 { u64 u; float2 f; };

// Packed fp32x2 FMA (Blackwell FFMA2) — exact fp32, 2x FFMA throughput.
__device__ __forceinline__ u64 fma2(u64 a, u64 b, u64 c) {
    u64 d;
    asm("fma.rn.f32x2 %0, %1, %2, %3;" : "=l"(d) : "l"(a), "l"(b), "l"(c));
    return d;
}

// 16-byte async global->shared copy (LDGSTS): no register pressure, overlaps
// with compute between issue and wait.
__device__ __forceinline__ void cp_async16(u32 smem_addr, const void* gptr) {
    asm volatile("cp.async.cg.shared.global [%0], [%1], 16;"
                 :: "r"(smem_addr), "l"(gptr));
}
__device__ __forceinline__ void cp_async_commit() {
    asm volatile("cp.async.commit_group;");
}
__device__ __forceinline__ void cp_async_wait_all() {
    asm volatile("cp.async.wait_group 0;");
}

__global__ __launch_bounds__(256, 2)
void attn_win_kernel(const float* __restrict__ Q,
                     const float* __restrict__ K,
                     const float* __restrict__ V,
                     const int*   __restrict__ prev_words,  // raw words of prev_max_attentions
                     float* __restrict__ out)
{
    extern __shared__ float smem[];
    float* Qs = smem + QS_OFF;
    float* Ks = smem + KS_OFF;   // K window during QK, then reused for V window
    float* Ps = smem + PS_OFF;

    const int tid = threadIdx.x;
    const int b   = blockIdx.y;
    const int t0  = blockIdx.x * TILE_T;

    // dtype sniff: int64 (little-endian, values < 2^31) has zero high words.
    int odd_or = prev_words[1] | prev_words[3] | prev_words[5] | prev_words[7] |
                 prev_words[9] | prev_words[11] | prev_words[13] | prev_words[15];
    const int prev = (odd_or == 0) ? prev_words[2 * b] : prev_words[b];

    float* Rout = out;                       // (B,T,512)
    float* Aout = out + R_ELEMS;             // (B,N,T), zero-filled below
    float* Mout = Aout + AL_ELEMS;           // (B,T)

    // ---------------- K window -> smem via cp.async (starts first) -----------
    {
        const char* Kg = (const char*)(K + ((size_t)b * NK + prev) * DD);
        #pragma unroll
        for (int it = 0; it < (WIN * DD / 4) / 256; ++it) {      // 16 iters
            int idx = tid + it * 256;
            int j   = idx >> 6;          // 0..63
            int d4  = idx & 63;
            u32 dst = (u32)__cvta_generic_to_shared(Ks + j * KS_STRIDE + d4 * 4);
            cp_async16(dst, Kg + (size_t)(j * 64 + d4) * 16);
        }
        cp_async_commit();
    }
    // ---------------- Q tile -> smem, and copy into R[:, :, 256:512] ---------
    // Overlaps with the in-flight K cp.asyncs.
    {
        const float4* Qg = (const float4*)(Q + ((size_t)b * TT + t0) * DD);
        #pragma unroll
        for (int it = 0; it < (TILE_T * DD / 4) / 256; ++it) {   // 8 iters
            int idx = tid + it * 256;
            int t   = idx >> 6;          // 0..31
            int d4  = idx & 63;          // 0..63 (float4 index)
            float4 q4 = __ldg(&Qg[t * 64 + d4]);
            *(float4*)(Qs + t * QS_STRIDE + d4 * 4) = q4;
            __stcs((float4*)(Rout + ((size_t)b * TT + t0 + t) * (2 * DD) + DD + d4 * 4), q4);
        }
    }
    cp_async_wait_all();
    __syncthreads();

    // ---------------- QK^T: scores[t][j], t in tile(32), j in 0..63 ----------
    // Thread: 2 t-rows x 4 j-cols, j = jh*32 + jg + 8*jj. Warp spans 8 j-lanes
    // x 4 t-groups => K loads 128B/1-phase (8 rows, bank-shift 4/row), Q loads
    // 4 addresses/1-phase. 6 crossbar phases per 16 FFMA2 warp-instr.
    {
        const int jg = tid & 7;
        const int tg = (tid >> 3) & 15;             // rows 2*tg, 2*tg+1
        const int jh = tid >> 7;                    // j half: 0 or 1
        const ulonglong2* q0p = (const ulonglong2*)(Qs + (size_t)(2 * tg) * QS_STRIDE);
        const ulonglong2* q1p = (const ulonglong2*)(Qs + (size_t)(2 * tg + 1) * QS_STRIDE);
        const ulonglong2* kp  = (const ulonglong2*)(Ks + (size_t)(jh * 32 + jg) * KS_STRIDE);
        const int KROW = 8 * (KS_STRIDE / 4);       // 8-row step in ulonglong2 units

        u64 accL[2][4], accH[2][4];
        #pragma unroll
        for (int i = 0; i < 2; ++i)
            #pragma unroll
            for (int jj = 0; jj < 4; ++jj) { accL[i][jj] = 0ull; accH[i][jj] = 0ull; }

        #pragma unroll 2
        for (int d4 = 0; d4 < DD / 4; ++d4) {
            ulonglong2 q0 = q0p[d4];
            ulonglong2 q1 = q1p[d4];
            ulonglong2 k0 = kp[d4];
            ulonglong2 k1 = kp[d4 + KROW];
            ulonglong2 k2 = kp[d4 + 2 * KROW];
            ulonglong2 k3 = kp[d4 + 3 * KROW];
            accL[0][0] = fma2(q0.x, k0.x, accL[0][0]);
            accH[0][0] = fma2(q0.y, k0.y, accH[0][0]);
            accL[1][0] = fma2(q1.x, k0.x, accL[1][0]);
            accH[1][0] = fma2(q1.y, k0.y, accH[1][0]);
            accL[0][1] = fma2(q0.x, k1.x, accL[0][1]);
            accH[0][1] = fma2(q0.y, k1.y, accH[0][1]);
            accL[1][1] = fma2(q1.x, k1.x, accL[1][1]);
            accH[1][1] = fma2(q1.y, k1.y, accH[1][1]);
            accL[0][2] = fma2(q0.x, k2.x, accL[0][2]);
            accH[0][2] = fma2(q0.y, k2.y, accH[0][2]);
            accL[1][2] = fma2(q1.x, k2.x, accL[1][2]);
            accH[1][2] = fma2(q1.y, k2.y, accH[1][2]);
            accL[0][3] = fma2(q0.x, k3.x, accL[0][3]);
            accH[0][3] = fma2(q0.y, k3.y, accH[0][3]);
            accL[1][3] = fma2(q1.x, k3.x, accL[1][3]);
            accH[1][3] = fma2(q1.y, k3.y, accH[1][3]);
        }
        #pragma unroll
        for (int i = 0; i < 2; ++i)
            #pragma unroll
            for (int jj = 0; jj < 4; ++jj) {
                UF2 lo, hi; lo.u = accL[i][jj]; hi.u = accH[i][jj];
                Ps[(2 * tg + i) * PS_STRIDE + jh * 32 + jg + 8 * jj] =
                    (lo.f.x + lo.f.y + hi.f.x + hi.f.y) * 0.0625f; // * rsqrt(256)
            }
    }
    __syncthreads();   // Ks (K data) now dead; Ps scores complete

    // ---------------- V window -> smem (reusing Ks) via cp.async -------------
    // Issued first so the copies fly while we zero-fill + run softmax.
    {
        const char* Vg = (const char*)(V + ((size_t)b * NK + prev) * DD);
        #pragma unroll
        for (int it = 0; it < (WIN * DD / 4) / 256; ++it) {      // 16 iters
            int idx = tid + it * 256;
            int j   = idx >> 6;          // 0..63
            int d4  = idx & 63;
            u32 dst = (u32)__cvta_generic_to_shared(Ks + j * KS_STRIDE + d4 * 4);
            cp_async16(dst, Vg + (size_t)(j * 64 + d4) * 16);
        }
        cp_async_commit();
    }

    // ---------------- zero-fill non-window rows of alignments ----------------
    // Independent of smem; drains to DRAM while V copies + softmax proceed.
    {
        const int rown = tid >> 3;          // 0..31
        const int c4   = tid & 7;           // float4 col of the 32 t-cols
        float* base = Aout + (size_t)b * NK * TT + t0 + 4 * c4;
        const float4 z = make_float4(0.f, 0.f, 0.f, 0.f);
        #pragma unroll 4
        for (int pass = 0; pass < NK / 32; ++pass) {
            int n = pass * 32 + rown;
            if ((unsigned)(n - prev) >= WIN)
                __stcs((float4*)(base + (size_t)n * TT), z);
        }
    }

    // ---------------- softmax over 64 window cols + argmax -------------------
    {
        const int lane = tid & 31;
        const int w    = tid >> 5;                 // 8 warps x 4 rows
        #pragma unroll
        for (int rr = 0; rr < TILE_T / 8; ++rr) {
            int r = w * (TILE_T / 8) + rr;
            float v0 = Ps[r * PS_STRIDE + lane];
            float v1 = Ps[r * PS_STRIDE + lane + 32];
            float bv; int bi;
            if (v0 >= v1) { bv = v0; bi = lane; } else { bv = v1; bi = lane + 32; }
            #pragma unroll
            for (int off = 16; off > 0; off >>= 1) {
                float ov = __shfl_xor_sync(0xffffffffu, bv, off);
                int   oi = __shfl_xor_sync(0xffffffffu, bi, off);
                if (ov > bv || (ov == bv && oi < bi)) { bv = ov; bi = oi; }
            }
            float e0 = __expf(v0 - bv);
            float e1 = __expf(v1 - bv);
            float s = e0 + e1;
            #pragma unroll
            for (int off = 16; off > 0; off >>= 1)
                s += __shfl_xor_sync(0xffffffffu, s, off);
            float inv = 1.0f / s;
            Ps[r * PS_STRIDE + lane]      = e0 * inv;
            Ps[r * PS_STRIDE + lane + 32] = e1 * inv;
            if (lane == 0)
                Mout[(size_t)b * TT + t0 + r] = (float)(prev + bi);
        }
    }
    cp_async_wait_all();
    __syncthreads();   // probs + V-in-smem visible to all

    // ---------------- scatter probs into window rows of alignments -----------
    {
        const int rown = tid >> 3;          // 0..31
        const int c4   = tid & 7;
        float* base = Aout + (size_t)b * NK * TT + t0 + 4 * c4;
        #pragma unroll
        for (int pass = 0; pass < 2; ++pass) {
            int j = pass * 32 + rown;       // 0..63 window col
            int t = 4 * c4;
            float4 v;
            v.x = Ps[(t + 0) * PS_STRIDE + j];
            v.y = Ps[(t + 1) * PS_STRIDE + j];
            v.z = Ps[(t + 2) * PS_STRIDE + j];
            v.w = Ps[(t + 3) * PS_STRIDE + j];
            __stcs((float4*)(base + (size_t)(prev + j) * TT), v);
        }
    }

    // ---------------- P @ V_window -> R[:, :, 0:256] --------------------------
    // V now in smem (contiguous 512B/warp => conflict-free, P loads broadcast).
    // Thread owns 8 t-rows and one float4 d-column.
    {
        const int d8 = tid & 63;                   // float4 index 0..63
        const int tg = tid >> 6;                   // 0..3 -> rows 8*tg..+7
        u64 acc[8][2];
        #pragma unroll
        for (int r = 0; r < 8; ++r) { acc[r][0] = 0ull; acc[r][1] = 0ull; }

        #pragma unroll 2
        for (int j4 = 0; j4 < WIN / 4; ++j4) {
            ulonglong2 vv[4];
            #pragma unroll
            for (int jj = 0; jj < 4; ++jj)
                vv[jj] = *(const ulonglong2*)(Ks + (size_t)(j4 * 4 + jj) * KS_STRIDE + d8 * 4);
            #pragma unroll
            for (int r = 0; r < 8; ++r) {
                float4 p4 = *(const float4*)(Ps + (tg * 8 + r) * PS_STRIDE + j4 * 4);
                UF2 pp;
                pp.f = make_float2(p4.x, p4.x);
                acc[r][0] = fma2(pp.u, vv[0].x, acc[r][0]);
                acc[r][1] = fma2(pp.u, vv[0].y, acc[r][1]);
                pp.f = make_float2(p4.y, p4.y);
                acc[r][0] = fma2(pp.u, vv[1].x, acc[r][0]);
                acc[r][1] = fma2(pp.u, vv[1].y, acc[r][1]);
                pp.f = make_float2(p4.z, p4.z);
                acc[r][0] = fma2(pp.u, vv[2].x, acc[r][0]);
                acc[r][1] = fma2(pp.u, vv[2].y, acc[r][1]);
                pp.f = make_float2(p4.w, p4.w);
                acc[r][0] = fma2(pp.u, vv[3].x, acc[r][0]);
                acc[r][1] = fma2(pp.u, vv[3].y, acc[r][1]);
            }
        }
        #pragma unroll
        for (int r = 0; r < 8; ++r) {
            float* dst = Rout + ((size_t)b * TT + t0 + tg * 8 + r) * (2 * DD) + 4 * d8;
            float4 o;
            o.x = ((UF2*)&acc[r][0])->f.x;  o.y = ((UF2*)&acc[r][0])->f.y;
            o.z = ((UF2*)&acc[r][1])->f.x;  o.w = ((UF2*)&acc[r][1])->f.y;
            __stcs((float4*)dst, o);
        }
    }
}

extern "C" void kernel_launch(void* const* d_in, const int* in_sizes, int n_in,
                              void* d_out, int out_size)
{
    const float* Q  = (const float*)d_in[0];
    const float* K  = (const float*)d_in[1];
    const float* V  = (const float*)d_in[2];
    const int* prevw = (const int*)d_in[3];   // int64 or int32, sniffed in-kernel
    float* out = (float*)d_out;

    cudaFuncSetAttribute(attn_win_kernel,
                         cudaFuncAttributeMaxDynamicSharedMemorySize, SMEM_BYTES);

    dim3 grid(TT / TILE_T, BB);
    attn_win_kernel<<<grid, 256, SMEM_BYTES, 0>>>(Q, K, V, prevw, out);
}

// round 9
// speedup vs baseline: 1.4008x; 1.1345x over previous
#include <cuda_runtime.h>

// Problem constants
#define BB      16
#define TT      1024
#define NK      1024
#define DD      256
#define WIN     64
#define TILE_T  32

// Shared-memory layout (floats). 260-float row stride => 4-bank shift per row.
#define QS_STRIDE   260
#define KS_STRIDE   260
#define PS_STRIDE   68

#define QS_OFF      0
#define KS_OFF      (TILE_T * QS_STRIDE)                 // 8320
#define PS_OFF      (KS_OFF + WIN * KS_STRIDE)           // 24960
#define SMEM_FLOATS (PS_OFF + TILE_T * PS_STRIDE)        // 27136 floats
#define SMEM_BYTES  (SMEM_FLOATS * 4)                    // 108544 B -> 2 CTAs/SM

// Output layout: R (B,T,512) | alignments (B,N,T) | max_attentions (B,T)
#define R_ELEMS   ((size_t)BB * TT * (2 * DD))           // 8,388,608
#define AL_ELEMS  ((size_t)BB * NK * TT)                 // 16,777,216

typedef unsigned long long u64;
typedef unsigned int       u32;

union UF2 { u64 u; float2 f; };

// Packed fp32x2 FMA (Blackwell FFMA2) — exact fp32, 2x FFMA throughput.
__device__ __forceinline__ u64 fma2(u64 a, u64 b, u64 c) {
    u64 d;
    asm("fma.rn.f32x2 %0, %1, %2, %3;" : "=l"(d) : "l"(a), "l"(b), "l"(c));
    return d;
}

// 16-byte async global->shared copy (LDGSTS).
__device__ __forceinline__ void cp_async16(u32 smem_addr, const void* gptr) {
    asm volatile("cp.async.cg.shared.global [%0], [%1], 16;"
                 :: "r"(smem_addr), "l"(gptr));
}
__device__ __forceinline__ void cp_async_commit() {
    asm volatile("cp.async.commit_group;");
}
__device__ __forceinline__ void cp_async_wait_all() {
    asm volatile("cp.async.wait_group 0;");
}

__global__ __launch_bounds__(256, 2)
void attn_win_kernel(const float* __restrict__ Q,
                     const float* __restrict__ K,
                     const float* __restrict__ V,
                     const int*   __restrict__ prev_words,  // raw words of prev_max_attentions
                     float* __restrict__ out)
{
    extern __shared__ float smem[];
    float* Qs = smem + QS_OFF;
    float* Ks = smem + KS_OFF;   // K window during QK, then reused for V window
    float* Ps = smem + PS_OFF;

    const int tid = threadIdx.x;
    const int b   = blockIdx.y;
    const int t0  = blockIdx.x * TILE_T;

    // dtype sniff: int64 (little-endian, values < 2^31) has zero high words.
    int odd_or = prev_words[1] | prev_words[3] | prev_words[5] | prev_words[7] |
                 prev_words[9] | prev_words[11] | prev_words[13] | prev_words[15];
    const int prev = (odd_or == 0) ? prev_words[2 * b] : prev_words[b];

    float* Rout = out;                       // (B,T,512)
    float* Aout = out + R_ELEMS;             // (B,N,T), zero-filled below
    float* Mout = Aout + AL_ELEMS;           // (B,T)

    // ---------------- K window -> smem via cp.async (starts first) -----------
    {
        const char* Kg = (const char*)(K + ((size_t)b * NK + prev) * DD);
        #pragma unroll
        for (int it = 0; it < (WIN * DD / 4) / 256; ++it) {      // 16 iters
            int idx = tid + it * 256;
            int j   = idx >> 6;          // 0..63
            int d4  = idx & 63;
            u32 dst = (u32)__cvta_generic_to_shared(Ks + j * KS_STRIDE + d4 * 4);
            cp_async16(dst, Kg + (size_t)(j * 64 + d4) * 16);
        }
        cp_async_commit();
    }
    // ---------------- Q tile -> smem, and copy into R[:, :, 256:512] ---------
    {
        const float4* Qg = (const float4*)(Q + ((size_t)b * TT + t0) * DD);
        #pragma unroll
        for (int it = 0; it < (TILE_T * DD / 4) / 256; ++it) {   // 8 iters
            int idx = tid + it * 256;
            int t   = idx >> 6;          // 0..31
            int d4  = idx & 63;          // 0..63 (float4 index)
            float4 q4 = __ldg(&Qg[t * 64 + d4]);
            *(float4*)(Qs + t * QS_STRIDE + d4 * 4) = q4;
            __stcs((float4*)(Rout + ((size_t)b * TT + t0 + t) * (2 * DD) + DD + d4 * 4), q4);
        }
    }
    cp_async_wait_all();
    __syncthreads();

    // =================== WARP-SPECIALIZED PHASE ==============================
    if (tid < 128) {
        // ------------- QK^T on warps 0-3: thread tile 4 t-rows x 4 j-cols ----
        // j = jh*32 + jg + 8*jj. Warp spans jg(8) x tg(4): K loads 8 unique
        // rows (4-bank shift -> conflict-free), Q loads 8 unique rows.
        // 8 LDS.128 feed 32 FFMA2 per iter (4 B/FFMA2 smem return traffic).
        const int jg = tid & 7;
        const int tg = (tid >> 3) & 7;              // rows 4*tg .. 4*tg+3
        const int jh = tid >> 6;                    // j half: 0 or 1
        const float* qb = Qs + (size_t)(tg * 4) * QS_STRIDE;
        const float* kb = Ks + (size_t)(jh * 32 + jg) * KS_STRIDE;

        u64 acc[4][4];
        #pragma unroll
        for (int i = 0; i < 4; ++i)
            #pragma unroll
            for (int c = 0; c < 4; ++c) acc[i][c] = 0ull;

        #pragma unroll 2
        for (int d4 = 0; d4 < DD / 4; ++d4) {
            ulonglong2 k0 = *(const ulonglong2*)(kb + 0 * 8 * KS_STRIDE + d4 * 4);
            ulonglong2 k1 = *(const ulonglong2*)(kb + 1 * 8 * KS_STRIDE + d4 * 4);
            ulonglong2 k2 = *(const ulonglong2*)(kb + 2 * 8 * KS_STRIDE + d4 * 4);
            ulonglong2 k3 = *(const ulonglong2*)(kb + 3 * 8 * KS_STRIDE + d4 * 4);
            #pragma unroll
            for (int i = 0; i < 4; ++i) {
                ulonglong2 q = *(const ulonglong2*)(qb + (size_t)i * QS_STRIDE + d4 * 4);
                acc[i][0] = fma2(q.x, k0.x, acc[i][0]);
                acc[i][0] = fma2(q.y, k0.y, acc[i][0]);
                acc[i][1] = fma2(q.x, k1.x, acc[i][1]);
                acc[i][1] = fma2(q.y, k1.y, acc[i][1]);
                acc[i][2] = fma2(q.x, k2.x, acc[i][2]);
                acc[i][2] = fma2(q.y, k2.y, acc[i][2]);
                acc[i][3] = fma2(q.x, k3.x, acc[i][3]);
                acc[i][3] = fma2(q.y, k3.y, acc[i][3]);
            }
        }
        #pragma unroll
        for (int i = 0; i < 4; ++i)
            #pragma unroll
            for (int c = 0; c < 4; ++c) {
                UF2 u; u.u = acc[i][c];
                Ps[(tg * 4 + i) * PS_STRIDE + jh * 32 + jg + 8 * c] =
                    (u.f.x + u.f.y) * 0.0625f;      // * rsqrt(256)
            }
    } else {
        // ------------- zero-fill non-window rows of alignments (warps 4-7) ---
        // Pure STG to global: overlaps fully with the QK compute above.
        const int t2   = tid - 128;
        const int rown = t2 >> 3;           // 0..15
        const int c4   = t2 & 7;            // float4 col of the 32 t-cols
        float* base = Aout + (size_t)b * NK * TT + t0 + 4 * c4;
        const float4 z = make_float4(0.f, 0.f, 0.f, 0.f);
        #pragma unroll 4
        for (int pass = 0; pass < NK / 16; ++pass) {
            int n = pass * 16 + rown;
            if ((unsigned)(n - prev) >= WIN)
                __stcs((float4*)(base + (size_t)n * TT), z);
        }
    }
    __syncthreads();   // Ks (K data) dead; Ps scores complete; zero-fill issued

    // ---------------- V window -> smem (reusing Ks) via cp.async -------------
    {
        const char* Vg = (const char*)(V + ((size_t)b * NK + prev) * DD);
        #pragma unroll
        for (int it = 0; it < (WIN * DD / 4) / 256; ++it) {      // 16 iters
            int idx = tid + it * 256;
            int j   = idx >> 6;          // 0..63
            int d4  = idx & 63;
            u32 dst = (u32)__cvta_generic_to_shared(Ks + j * KS_STRIDE + d4 * 4);
            cp_async16(dst, Vg + (size_t)(j * 64 + d4) * 16);
        }
        cp_async_commit();
    }

    // ---------------- softmax over 64 window cols + argmax -------------------
    {
        const int lane = tid & 31;
        const int w    = tid >> 5;                 // 8 warps x 4 rows
        #pragma unroll
        for (int rr = 0; rr < TILE_T / 8; ++rr) {
            int r = w * (TILE_T / 8) + rr;
            float v0 = Ps[r * PS_STRIDE + lane];
            float v1 = Ps[r * PS_STRIDE + lane + 32];
            float bv; int bi;
            if (v0 >= v1) { bv = v0; bi = lane; } else { bv = v1; bi = lane + 32; }
            #pragma unroll
            for (int off = 16; off > 0; off >>= 1) {
                float ov = __shfl_xor_sync(0xffffffffu, bv, off);
                int   oi = __shfl_xor_sync(0xffffffffu, bi, off);
                if (ov > bv || (ov == bv && oi < bi)) { bv = ov; bi = oi; }
            }
            float e0 = __expf(v0 - bv);
            float e1 = __expf(v1 - bv);
            float s = e0 + e1;
            #pragma unroll
            for (int off = 16; off > 0; off >>= 1)
                s += __shfl_xor_sync(0xffffffffu, s, off);
            float inv = 1.0f / s;
            Ps[r * PS_STRIDE + lane]      = e0 * inv;
            Ps[r * PS_STRIDE + lane + 32] = e1 * inv;
            if (lane == 0)
                Mout[(size_t)b * TT + t0 + r] = (float)(prev + bi);
        }
    }
    cp_async_wait_all();
    __syncthreads();   // probs + V-in-smem visible to all

    // ---------------- scatter probs into window rows of alignments -----------
    {
        const int rown = tid >> 3;          // 0..31
        const int c4   = tid & 7;
        float* base = Aout + (size_t)b * NK * TT + t0 + 4 * c4;
        #pragma unroll
        for (int pass = 0; pass < 2; ++pass) {
            int j = pass * 32 + rown;       // 0..63 window col
            int t = 4 * c4;
            float4 v;
            v.x = Ps[(t + 0) * PS_STRIDE + j];
            v.y = Ps[(t + 1) * PS_STRIDE + j];
            v.z = Ps[(t + 2) * PS_STRIDE + j];
            v.w = Ps[(t + 3) * PS_STRIDE + j];
            __stcs((float4*)(base + (size_t)(prev + j) * TT), v);
        }
    }

    // ---------------- P @ V_window -> R[:, :, 0:256] --------------------------
    // V in smem; thread owns 8 t-rows and one float4 d-column.
    {
        const int d8 = tid & 63;                   // float4 index 0..63
        const int tg = tid >> 6;                   // 0..3 -> rows 8*tg..+7
        u64 acc[8][2];
        #pragma unroll
        for (int r = 0; r < 8; ++r) { acc[r][0] = 0ull; acc[r][1] = 0ull; }

        #pragma unroll 2
        for (int j4 = 0; j4 < WIN / 4; ++j4) {
            ulonglong2 vv[4];
            #pragma unroll
            for (int jj = 0; jj < 4; ++jj)
                vv[jj] = *(const ulonglong2*)(Ks + (size_t)(j4 * 4 + jj) * KS_STRIDE + d8 * 4);
            #pragma unroll
            for (int r = 0; r < 8; ++r) {
                float4 p4 = *(const float4*)(Ps + (tg * 8 + r) * PS_STRIDE + j4 * 4);
                UF2 pp;
                pp.f = make_float2(p4.x, p4.x);
                acc[r][0] = fma2(pp.u, vv[0].x, acc[r][0]);
                acc[r][1] = fma2(pp.u, vv[0].y, acc[r][1]);
                pp.f = make_float2(p4.y, p4.y);
                acc[r][0] = fma2(pp.u, vv[1].x, acc[r][0]);
                acc[r][1] = fma2(pp.u, vv[1].y, acc[r][1]);
                pp.f = make_float2(p4.z, p4.z);
                acc[r][0] = fma2(pp.u, vv[2].x, acc[r][0]);
                acc[r][1] = fma2(pp.u, vv[2].y, acc[r][1]);
                pp.f = make_float2(p4.w, p4.w);
                acc[r][0] = fma2(pp.u, vv[3].x, acc[r][0]);
                acc[r][1] = fma2(pp.u, vv[3].y, acc[r][1]);
            }
        }
        #pragma unroll
        for (int r = 0; r < 8; ++r) {
            float* dst = Rout + ((size_t)b * TT + t0 + tg * 8 + r) * (2 * DD) + 4 * d8;
            float4 o;
            o.x = ((UF2*)&acc[r][0])->f.x;  o.y = ((UF2*)&acc[r][0])->f.y;
            o.z = ((UF2*)&acc[r][1])->f.x;  o.w = ((UF2*)&acc[r][1])->f.y;
            __stcs((float4*)dst, o);
        }
    }
}

extern "C" void kernel_launch(void* const* d_in, const int* in_sizes, int n_in,
                              void* d_out, int out_size)
{
    const float* Q  = (const float*)d_in[0];
    const float* K  = (const float*)d_in[1];
    const float* V  = (const float*)d_in[2];
    const int* prevw = (const int*)d_in[3];   // int64 or int32, sniffed in-kernel
    float* out = (float*)d_out;

    cudaFuncSetAttribute(attn_win_kernel,
                         cudaFuncAttributeMaxDynamicSharedMemorySize, SMEM_BYTES);

    dim3 grid(TT / TILE_T, BB);
    attn_win_kernel<<<grid, 256, SMEM_BYTES, 0>>>(Q, K, V, prevw, out);
}